// round 4
// baseline (speedup 1.0000x reference)
#include <cuda_runtime.h>
#include <math.h>

#define TT 512
#define BB 32
#define KD 1024
#define GD 4096
#define NBLK 128
#define NTHR 256

// Scratch (static __device__ allowed): x_proj [T,B,4C] = 256 MB,
// h state double-buffered transposed [c][b], barrier counter.
__device__ float g_xproj[(size_t)TT * BB * GD];
__device__ float g_hbuf[2][KD * BB];
__device__ unsigned g_bar_cnt;

// ---------------------------------------------------------------------------
// Kernel 1: broadcast h0 into h state, reset barrier
// ---------------------------------------------------------------------------
__global__ void init_state_kernel(const float* __restrict__ h0) {
    int i = blockIdx.x * blockDim.x + threadIdx.x;   // 0 .. 32767
    int c = i >> 5;
    g_hbuf[0][i] = h0[c];
    if (i == 0) g_bar_cnt = 0u;
}

// ---------------------------------------------------------------------------
// Kernel 2: x_proj GEMM (unchanged from R2; ~5.5 ms, next round's target)
// ---------------------------------------------------------------------------
__global__ void __launch_bounds__(256)
xproj_gemm_kernel(const float* __restrict__ A,
                  const float* __restrict__ W,
                  const float* __restrict__ b_ih,
                  const float* __restrict__ b_hh) {
    __shared__ float As[8][128];
    __shared__ float Ws[8][128];

    const int tid = threadIdx.x;
    const int bm  = blockIdx.y * 128;
    const int bn  = blockIdx.x * 128;
    const int row = tid >> 1;
    const int kof = (tid & 1) * 4;
    const int tx  = tid & 15;
    const int ty  = tid >> 4;

    const float* Aptr = A + (size_t)(bm + row) * KD + kof;
    const float* Wptr = W + (size_t)(bn + row) * KD + kof;

    float4 av = *(const float4*)Aptr;
    float4 wv = *(const float4*)Wptr;

    float acc[8][8];
#pragma unroll
    for (int i = 0; i < 8; i++)
#pragma unroll
        for (int j = 0; j < 8; j++) acc[i][j] = 0.f;

    for (int k0 = 0; k0 < KD; k0 += 8) {
        __syncthreads();
        As[kof + 0][row] = av.x; As[kof + 1][row] = av.y;
        As[kof + 2][row] = av.z; As[kof + 3][row] = av.w;
        Ws[kof + 0][row] = wv.x; Ws[kof + 1][row] = wv.y;
        Ws[kof + 2][row] = wv.z; Ws[kof + 3][row] = wv.w;
        __syncthreads();
        if (k0 + 8 < KD) {
            av = *(const float4*)(Aptr + k0 + 8);
            wv = *(const float4*)(Wptr + k0 + 8);
        }
#pragma unroll
        for (int k = 0; k < 8; k++) {
            float4 a0 = *(const float4*)&As[k][ty * 8];
            float4 a1 = *(const float4*)&As[k][ty * 8 + 4];
            float4 w0 = *(const float4*)&Ws[k][tx * 8];
            float4 w1 = *(const float4*)&Ws[k][tx * 8 + 4];
            float am[8] = {a0.x, a0.y, a0.z, a0.w, a1.x, a1.y, a1.z, a1.w};
            float wm[8] = {w0.x, w0.y, w0.z, w0.w, w1.x, w1.y, w1.z, w1.w};
#pragma unroll
            for (int i = 0; i < 8; i++)
#pragma unroll
                for (int j = 0; j < 8; j++) acc[i][j] += am[i] * wm[j];
        }
    }

    float bias[8];
#pragma unroll
    for (int j = 0; j < 8; j++) {
        int n = bn + tx * 8 + j;
        bias[j] = b_ih[n] + b_hh[n];
    }
#pragma unroll
    for (int i = 0; i < 8; i++) {
        size_t off = (size_t)(bm + ty * 8 + i) * GD + bn + tx * 8;
        float4 o0, o1;
        o0.x = acc[i][0] + bias[0]; o0.y = acc[i][1] + bias[1];
        o0.z = acc[i][2] + bias[2]; o0.w = acc[i][3] + bias[3];
        o1.x = acc[i][4] + bias[4]; o1.y = acc[i][5] + bias[5];
        o1.z = acc[i][6] + bias[6]; o1.w = acc[i][7] + bias[7];
        *(float4*)&g_xproj[off]     = o0;
        *(float4*)&g_xproj[off + 4] = o1;
    }
}

// ---------------------------------------------------------------------------
// Kernel 3: PERSISTENT recurrence kernel. 128 blocks x 256 threads, 1/SM.
// Block owns 32 w_hh rows (4 gates x 8 c) in SMEM for all 512 steps.
// Per step: 8 warps split K (128 each), microtile 4r x 8b, smem reduction,
// fused gate epilogue, register-resident c-state, atomic-counter barrier.
// ---------------------------------------------------------------------------
extern __shared__ float smem_dyn[];

__global__ void __launch_bounds__(NTHR, 1)
lstm_persistent_kernel(const float* __restrict__ w_hh,
                       const float* __restrict__ c0,
                       float* __restrict__ out) {
    float* w_s = smem_dyn;            // [1024][32] k-major, 128 KB
    float* hp  = smem_dyn + 32768;    // 8192 floats = 32 KB: staging + partials

    const int tid  = threadIdx.x;
    const int blk  = blockIdx.x;
    const int c_base = blk * 8;

    // ---- load w_hh slice transposed into smem: w_s[k*32 + r], r = gate*8+cl
    {
        const int r    = tid & 31;            // 0..31
        const int kg   = tid >> 5;            // 0..7
        const int gate = r >> 3;
        const int cl   = r & 7;
        const float* wrow = w_hh + (size_t)(gate * KD + c_base + cl) * KD;
#pragma unroll 8
        for (int kk = 0; kk < 128; kk++) {
            int k = kg * 128 + kk;
            w_s[k * 32 + r] = wrow[k];        // STS conflict-free (lanes r)
        }
    }

    // ---- FMA identities: warp = k-slice, lane -> (r_grp, b_grp)
    const int warp  = tid >> 5;
    const int lane  = tid & 31;
    const int r_grp = lane >> 2;              // rows r_grp*4 .. +3
    const int b_grp = lane & 3;               // b   b_grp*8 .. +7
    float* my_stage = hp + warp * 1024;       // 512-float staging buffer

    // ---- epilogue identities: warp = cl, lane = b
    const int eb  = lane;
    const int ecl = warp;
    const int ec  = c_base + ecl;
    float c_state = c0[ec];                   // register-resident for all T

    __syncthreads();

    for (int t = 0; t < TT; t++) {
        const float* hin  = g_hbuf[t & 1];
        float*       hout = g_hbuf[(t & 1) ^ 1];

        // prefetch this step's xproj gate values (hidden under k-loop)
        const float* xp = g_xproj + ((size_t)t * BB + eb) * GD + ec;
        float x_i = __ldg(xp);
        float x_f = __ldg(xp + KD);
        float x_g = __ldg(xp + 2 * KD);
        float x_o = __ldg(xp + 3 * KD);

        // prefetch h chunk 0 (L2, bypass incoherent L1)
        const float* hsrc = hin + warp * 128 * 32;
        float4 pf[4];
#pragma unroll
        for (int i = 0; i < 4; i++)
            pf[i] = __ldcg((const float4*)(hsrc + i * 128 + lane * 4));

        float acc[4][8];
#pragma unroll
        for (int ri = 0; ri < 4; ri++)
#pragma unroll
            for (int bi = 0; bi < 8; bi++) acc[ri][bi] = 0.f;

        for (int ch = 0; ch < 8; ch++) {
            // stage prefetched chunk into smem
#pragma unroll
            for (int i = 0; i < 4; i++)
                *(float4*)(my_stage + i * 128 + lane * 4) = pf[i];
            __syncwarp();
            // prefetch next chunk (overlaps compute)
            if (ch < 7) {
#pragma unroll
                for (int i = 0; i < 4; i++)
                    pf[i] = __ldcg((const float4*)(hsrc + (ch + 1) * 512 + i * 128 + lane * 4));
            }
            const float* wk = w_s + (warp * 128 + ch * 16) * 32;
#pragma unroll
            for (int kk = 0; kk < 16; kk++) {
                float4 h0 = *(const float4*)(my_stage + kk * 32 + b_grp * 8);
                float4 h1 = *(const float4*)(my_stage + kk * 32 + b_grp * 8 + 4);
                float4 wv = *(const float4*)(wk + kk * 32 + r_grp * 4);
                float hv[8] = {h0.x, h0.y, h0.z, h0.w, h1.x, h1.y, h1.z, h1.w};
                float wr[4] = {wv.x, wv.y, wv.z, wv.w};
#pragma unroll
                for (int ri = 0; ri < 4; ri++)
#pragma unroll
                    for (int bi = 0; bi < 8; bi++)
                        acc[ri][bi] += wr[ri] * hv[bi];
            }
            __syncwarp();
        }

        // ---- write per-warp partials: part[warp*1024 + r*32 + b]
        __syncthreads();
#pragma unroll
        for (int ri = 0; ri < 4; ri++) {
            int r = r_grp * 4 + ri;
            float4 p0 = make_float4(acc[ri][0], acc[ri][1], acc[ri][2], acc[ri][3]);
            float4 p1 = make_float4(acc[ri][4], acc[ri][5], acc[ri][6], acc[ri][7]);
            *(float4*)(hp + warp * 1024 + r * 32 + b_grp * 8)     = p0;
            *(float4*)(hp + warp * 1024 + r * 32 + b_grp * 8 + 4) = p1;
        }
        __syncthreads();

        // ---- reduce 8 partials + fused gates (thread = (cl, b))
        float gi = x_i, gf = x_f, gg = x_g, go = x_o;
#pragma unroll
        for (int j = 0; j < 8; j++) {
            const float* p = hp + j * 1024 + ecl * 32 + eb;
            gi += p[0 * 8 * 32];
            gf += p[1 * 8 * 32];
            gg += p[2 * 8 * 32];
            go += p[3 * 8 * 32];
        }
        float ig = 1.f / (1.f + __expf(-gi));
        float fg = 1.f / (1.f + __expf(-gf));
        float gt = tanhf(gg);
        float og = 1.f / (1.f + __expf(-go));
        c_state  = fg * c_state + ig * gt;
        float hn = og * tanhf(c_state);

        out[((size_t)t * BB + eb) * KD + ec] = hn;
        __stcg(&hout[ec * 32 + eb], hn);      // L2-visible for other SMs

        // ---- inter-block barrier (accumulating counter)
        if (t != TT - 1) {
            __threadfence();
            __syncthreads();
            if (tid == 0) {
                atomicAdd(&g_bar_cnt, 1u);
                unsigned target = (unsigned)(t + 1) * NBLK;
                while (*(volatile unsigned*)&g_bar_cnt < target) {
                    __nanosleep(64);
                }
            }
            __syncthreads();
            __threadfence();
        }
    }
}

// ---------------------------------------------------------------------------
extern "C" void kernel_launch(void* const* d_in, const int* in_sizes, int n_in,
                              void* d_out, int out_size) {
    const float* embs = (const float*)d_in[0];
    const float* w_ih = (const float*)d_in[1];
    const float* w_hh = (const float*)d_in[2];
    const float* b_ih = (const float*)d_in[3];
    const float* b_hh = (const float*)d_in[4];
    const float* h0   = (const float*)d_in[5];
    const float* c0   = (const float*)d_in[6];
    float* out = (float*)d_out;

    init_state_kernel<<<128, 256>>>(h0);

    dim3 g1(GD / 128, (TT * BB) / 128);
    xproj_gemm_kernel<<<g1, 256>>>(embs, w_ih, b_ih, b_hh);

    static int smem_set = 0;
    const int smem_bytes = (32768 + 8192) * (int)sizeof(float);  // 160 KB
    if (!smem_set) {
        cudaFuncSetAttribute(lstm_persistent_kernel,
                             cudaFuncAttributeMaxDynamicSharedMemorySize,
                             smem_bytes);
        smem_set = 1;
    }
    lstm_persistent_kernel<<<NBLK, NTHR, smem_bytes>>>(w_hh, c0, out);
}

// round 5
// speedup vs baseline: 1.0434x; 1.0434x over previous
#include <cuda_runtime.h>
#include <math.h>

#define TT 512
#define BB 32
#define KD 1024
#define GD 4096
#define NBLK 128
#define NTHR 512

// Scratch: x_proj [T,B,4C] = 256 MB, h double-buffered transposed [c][b],
// inter-block barrier counter, per-y-rowchunk xproj completion flags.
__device__ float g_xproj[(size_t)TT * BB * GD];
__device__ float g_hbuf[2][KD * BB];
__device__ unsigned g_bar_cnt;
__device__ unsigned g_xflag[128];   // y-chunk -> # of n-tiles finished (target 32)

// named barriers: recurrence group (warps 0-7), gemm group (warps 8-15)
#define NB_REC() asm volatile("bar.sync 1, 256;" ::: "memory")
#define NB_GEM() asm volatile("bar.sync 2, 256;" ::: "memory")

// ---------------------------------------------------------------------------
// Kernel 1: broadcast h0 into h state, reset barrier + flags
// ---------------------------------------------------------------------------
__global__ void init_state_kernel(const float* __restrict__ h0) {
    int i = blockIdx.x * blockDim.x + threadIdx.x;   // 0 .. 32767
    int c = i >> 5;
    g_hbuf[0][i] = h0[c];
    if (i == 0) g_bar_cnt = 0u;
    if (i < 128) g_xflag[i] = 0u;
}

// ---------------------------------------------------------------------------
// Fused persistent kernel: 128 blocks x 512 threads, 1 block/SM.
//   warps 0-7  : LSTM recurrence (R4 design: w_hh slice resident in smem,
//                K split 8 ways, smem partial reduction, register c-state,
//                atomic-counter inter-block barrier).
//   warps 8-15 : xproj producer.  Block b computes n-tile (b&31) for y-rows
//                (b>>5)+4i, i=0..31 (time-ordered), sets g_xflag[y] when done.
// Recurrence step t additionally waits g_xflag[t>>2]==32 (folded into the
// per-step barrier critical section).
// ---------------------------------------------------------------------------
extern __shared__ float smem_dyn[];

__global__ void __launch_bounds__(NTHR, 1)
lstm_fused_kernel(const float* __restrict__ embs,
                  const float* __restrict__ w_ih,
                  const float* __restrict__ w_hh,
                  const float* __restrict__ b_ih,
                  const float* __restrict__ b_hh,
                  const float* __restrict__ c0,
                  float* __restrict__ out) {
    float* w_s = smem_dyn;            // [1024][32] k-major, 128 KB
    float* hp  = smem_dyn + 32768;    // 8 KB staging x8 warps / 32 KB partials
    float* xAs = smem_dyn + 40960;    // xproj A tile [8][128]
    float* xWs = smem_dyn + 41984;    // xproj W tile [8][128]

    const int tid = threadIdx.x;
    const int blk = blockIdx.x;

    if (tid < 256) {
        // =================== RECURRENCE GROUP (warps 0-7) ===================
        const int c_base = blk * 8;

        // load w_hh slice transposed into smem: w_s[k*32 + r], r = gate*8+cl
        {
            const int r    = tid & 31;
            const int kg   = tid >> 5;
            const int gate = r >> 3;
            const int cl   = r & 7;
            const float* wrow = w_hh + (size_t)(gate * KD + c_base + cl) * KD;
#pragma unroll 8
            for (int kk = 0; kk < 128; kk++) {
                int k = kg * 128 + kk;
                w_s[k * 32 + r] = wrow[k];
            }
        }

        const int warp  = tid >> 5;
        const int lane  = tid & 31;
        const int r_grp = lane >> 2;
        const int b_grp = lane & 3;
        float* my_stage = hp + warp * 1024;

        const int eb  = lane;
        const int ecl = warp;
        const int ec  = c_base + ecl;
        float c_state = c0[ec];

        NB_REC();

        // wait for xproj of timestep 0
        if (tid == 0) {
            while (*(volatile unsigned*)&g_xflag[0] < 32u) { __nanosleep(64); }
        }
        NB_REC();
        __threadfence();

        for (int t = 0; t < TT; t++) {
            const float* hin  = g_hbuf[t & 1];
            float*       hout = g_hbuf[(t & 1) ^ 1];

            const float* xp = g_xproj + ((size_t)t * BB + eb) * GD + ec;
            float x_i = __ldcg(xp);
            float x_f = __ldcg(xp + KD);
            float x_g = __ldcg(xp + 2 * KD);
            float x_o = __ldcg(xp + 3 * KD);

            const float* hsrc = hin + warp * 128 * 32;
            float4 pf[4];
#pragma unroll
            for (int i = 0; i < 4; i++)
                pf[i] = __ldcg((const float4*)(hsrc + i * 128 + lane * 4));

            float acc[4][8];
#pragma unroll
            for (int ri = 0; ri < 4; ri++)
#pragma unroll
                for (int bi = 0; bi < 8; bi++) acc[ri][bi] = 0.f;

            for (int ch = 0; ch < 8; ch++) {
#pragma unroll
                for (int i = 0; i < 4; i++)
                    *(float4*)(my_stage + i * 128 + lane * 4) = pf[i];
                __syncwarp();
                if (ch < 7) {
#pragma unroll
                    for (int i = 0; i < 4; i++)
                        pf[i] = __ldcg((const float4*)(hsrc + (ch + 1) * 512 + i * 128 + lane * 4));
                }
                const float* wk = w_s + (warp * 128 + ch * 16) * 32;
#pragma unroll
                for (int kk = 0; kk < 16; kk++) {
                    float4 h0v = *(const float4*)(my_stage + kk * 32 + b_grp * 8);
                    float4 h1v = *(const float4*)(my_stage + kk * 32 + b_grp * 8 + 4);
                    float4 wv  = *(const float4*)(wk + kk * 32 + r_grp * 4);
                    float hv[8] = {h0v.x, h0v.y, h0v.z, h0v.w, h1v.x, h1v.y, h1v.z, h1v.w};
                    float wr[4] = {wv.x, wv.y, wv.z, wv.w};
#pragma unroll
                    for (int ri = 0; ri < 4; ri++)
#pragma unroll
                        for (int bi = 0; bi < 8; bi++)
                            acc[ri][bi] += wr[ri] * hv[bi];
                }
                __syncwarp();
            }

            NB_REC();
#pragma unroll
            for (int ri = 0; ri < 4; ri++) {
                int r = r_grp * 4 + ri;
                float4 p0 = make_float4(acc[ri][0], acc[ri][1], acc[ri][2], acc[ri][3]);
                float4 p1 = make_float4(acc[ri][4], acc[ri][5], acc[ri][6], acc[ri][7]);
                *(float4*)(hp + warp * 1024 + r * 32 + b_grp * 8)     = p0;
                *(float4*)(hp + warp * 1024 + r * 32 + b_grp * 8 + 4) = p1;
            }
            NB_REC();

            float gi = x_i, gf = x_f, gg = x_g, go = x_o;
#pragma unroll
            for (int j = 0; j < 8; j++) {
                const float* p = hp + j * 1024 + ecl * 32 + eb;
                gi += p[0 * 8 * 32];
                gf += p[1 * 8 * 32];
                gg += p[2 * 8 * 32];
                go += p[3 * 8 * 32];
            }
            float ig = 1.f / (1.f + __expf(-gi));
            float fg = 1.f / (1.f + __expf(-gf));
            float gt = tanhf(gg);
            float og = 1.f / (1.f + __expf(-go));
            c_state  = fg * c_state + ig * gt;
            float hn = og * tanhf(c_state);

            out[((size_t)t * BB + eb) * KD + ec] = hn;
            __stcg(&hout[ec * 32 + eb], hn);

            // inter-block barrier + next-step xproj-ready wait
            if (t != TT - 1) {
                __threadfence();
                NB_REC();
                if (tid == 0) {
                    atomicAdd(&g_bar_cnt, 1u);
                    unsigned target = (unsigned)(t + 1) * NBLK;
                    while (*(volatile unsigned*)&g_bar_cnt < target) {
                        __nanosleep(32);
                    }
                    unsigned ychunk = (unsigned)(t + 1) >> 2;
                    while (*(volatile unsigned*)&g_xflag[ychunk] < 32u) {
                        __nanosleep(32);
                    }
                }
                NB_REC();
                __threadfence();
            }
        }
    } else {
        // ==================== XPROJ GROUP (warps 8-15) ======================
        const int tid2 = tid - 256;
        const int x_b  = blk & 31;        // n tile
        const int y_b  = blk >> 5;        // 0..3
        const int bn   = x_b * 128;

        const int row = tid2 >> 1;
        const int kof = (tid2 & 1) * 4;
        const int tx  = tid2 & 15;
        const int ty  = tid2 >> 4;

        float bias[8];
#pragma unroll
        for (int j = 0; j < 8; j++) {
            int n = bn + tx * 8 + j;
            bias[j] = __ldg(&b_ih[n]) + __ldg(&b_hh[n]);
        }
        const float* Wptr = w_ih + (size_t)(bn + row) * KD + kof;

        for (int it = 0; it < 32; it++) {
            const int y  = y_b + 4 * it;
            const int bm = y * 128;
            const float* Aptr = embs + (size_t)(bm + row) * KD + kof;

            float4 av = *(const float4*)Aptr;
            float4 wv = *(const float4*)Wptr;

            float acc[8][8];
#pragma unroll
            for (int i = 0; i < 8; i++)
#pragma unroll
                for (int j = 0; j < 8; j++) acc[i][j] = 0.f;

            for (int k0 = 0; k0 < KD; k0 += 8) {
                NB_GEM();
                xAs[(kof + 0) * 128 + row] = av.x;
                xAs[(kof + 1) * 128 + row] = av.y;
                xAs[(kof + 2) * 128 + row] = av.z;
                xAs[(kof + 3) * 128 + row] = av.w;
                xWs[(kof + 0) * 128 + row] = wv.x;
                xWs[(kof + 1) * 128 + row] = wv.y;
                xWs[(kof + 2) * 128 + row] = wv.z;
                xWs[(kof + 3) * 128 + row] = wv.w;
                NB_GEM();
                if (k0 + 8 < KD) {
                    av = *(const float4*)(Aptr + k0 + 8);
                    wv = *(const float4*)(Wptr + k0 + 8);
                }
#pragma unroll
                for (int k = 0; k < 8; k++) {
                    float4 a0 = *(const float4*)&xAs[k * 128 + ty * 8];
                    float4 a1 = *(const float4*)&xAs[k * 128 + ty * 8 + 4];
                    float4 w0 = *(const float4*)&xWs[k * 128 + tx * 8];
                    float4 w1 = *(const float4*)&xWs[k * 128 + tx * 8 + 4];
                    float am[8] = {a0.x, a0.y, a0.z, a0.w, a1.x, a1.y, a1.z, a1.w};
                    float wm[8] = {w0.x, w0.y, w0.z, w0.w, w1.x, w1.y, w1.z, w1.w};
#pragma unroll
                    for (int i = 0; i < 8; i++)
#pragma unroll
                        for (int j = 0; j < 8; j++) acc[i][j] += am[i] * wm[j];
                }
            }

#pragma unroll
            for (int i = 0; i < 8; i++) {
                size_t off = (size_t)(bm + ty * 8 + i) * GD + bn + tx * 8;
                float4 o0, o1;
                o0.x = acc[i][0] + bias[0]; o0.y = acc[i][1] + bias[1];
                o0.z = acc[i][2] + bias[2]; o0.w = acc[i][3] + bias[3];
                o1.x = acc[i][4] + bias[4]; o1.y = acc[i][5] + bias[5];
                o1.z = acc[i][6] + bias[6]; o1.w = acc[i][7] + bias[7];
                *(float4*)&g_xproj[off]     = o0;
                *(float4*)&g_xproj[off + 4] = o1;
            }

            __threadfence();
            NB_GEM();
            if (tid2 == 0) atomicAdd(&g_xflag[y], 1u);
        }
    }
}

// ---------------------------------------------------------------------------
extern "C" void kernel_launch(void* const* d_in, const int* in_sizes, int n_in,
                              void* d_out, int out_size) {
    const float* embs = (const float*)d_in[0];
    const float* w_ih = (const float*)d_in[1];
    const float* w_hh = (const float*)d_in[2];
    const float* b_ih = (const float*)d_in[3];
    const float* b_hh = (const float*)d_in[4];
    const float* h0   = (const float*)d_in[5];
    const float* c0   = (const float*)d_in[6];
    float* out = (float*)d_out;

    init_state_kernel<<<128, 256>>>(h0);

    static int smem_set = 0;
    const int smem_bytes = (32768 + 8192 + 2048) * (int)sizeof(float);  // 168 KB
    if (!smem_set) {
        cudaFuncSetAttribute(lstm_fused_kernel,
                             cudaFuncAttributeMaxDynamicSharedMemorySize,
                             smem_bytes);
        smem_set = 1;
    }
    lstm_fused_kernel<<<NBLK, NTHR, smem_bytes>>>(embs, w_ih, w_hh, b_ih, b_hh,
                                                  c0, out);
}

// round 6
// speedup vs baseline: 1.1659x; 1.1174x over previous
#include <cuda_runtime.h>
#include <cuda_bf16.h>
#include <math.h>

#define TT 512
#define BB 32
#define KD 1024
#define GD 4096
#define NBLK 128
#define NTHR 512

// Scratch: x_proj [T,B,4C] = 256 MB, h double-buffered transposed [c][b],
// inter-block barrier counter, per-y-rowchunk xproj completion flags.
__device__ float g_xproj[(size_t)TT * BB * GD];
__device__ float g_hbuf[2][KD * BB];
__device__ unsigned g_bar_cnt;
__device__ unsigned g_xflag[128];   // y-chunk -> # of n-tiles finished (target 32)

#define NB_REC() asm volatile("bar.sync 1, 256;" ::: "memory")
#define NB_GEM() asm volatile("bar.sync 2, 256;" ::: "memory")

// ---------------------------------------------------------------------------
__global__ void init_state_kernel(const float* __restrict__ h0) {
    int i = blockIdx.x * blockDim.x + threadIdx.x;
    int c = i >> 5;
    g_hbuf[0][i] = h0[c];
    if (i == 0) g_bar_cnt = 0u;
    if (i < 128) g_xflag[i] = 0u;
}

// ---------------------------------------------------------------------------
__device__ __forceinline__ void mma16816(float* c,
                                         unsigned a0, unsigned a1, unsigned a2, unsigned a3,
                                         unsigned b0, unsigned b1) {
    asm volatile(
        "mma.sync.aligned.m16n8k16.row.col.f32.bf16.bf16.f32 "
        "{%0,%1,%2,%3}, {%4,%5,%6,%7}, {%8,%9}, {%0,%1,%2,%3};\n"
        : "+f"(c[0]), "+f"(c[1]), "+f"(c[2]), "+f"(c[3])
        : "r"(a0), "r"(a1), "r"(a2), "r"(a3), "r"(b0), "r"(b1));
}

// convert float4 -> hi/lo bf16 and store into padded smem slab [128][20]
__device__ __forceinline__ void cvt_store_slab(__nv_bfloat16* hi, __nv_bfloat16* lo,
                                               int row, int seg, float4 v) {
    int idx = row * 20 + seg * 4;
    __nv_bfloat16 hx = __float2bfloat16_rn(v.x);
    __nv_bfloat16 hy = __float2bfloat16_rn(v.y);
    __nv_bfloat16 hz = __float2bfloat16_rn(v.z);
    __nv_bfloat16 hw = __float2bfloat16_rn(v.w);
    float lx = v.x - __bfloat162float(hx);
    float ly = v.y - __bfloat162float(hy);
    float lz = v.z - __bfloat162float(hz);
    float lw = v.w - __bfloat162float(hw);
    __nv_bfloat162 h01; h01.x = hx; h01.y = hy;
    __nv_bfloat162 h23; h23.x = hz; h23.y = hw;
    *(__nv_bfloat162*)&hi[idx]     = h01;
    *(__nv_bfloat162*)&hi[idx + 2] = h23;
    *(__nv_bfloat162*)&lo[idx]     = __floats2bfloat162_rn(lx, ly);
    *(__nv_bfloat162*)&lo[idx + 2] = __floats2bfloat162_rn(lz, lw);
}

// ---------------------------------------------------------------------------
// Fused persistent kernel: 128 blocks x 512 threads, 1 block/SM.
//   warps 0-7  : fp32 LSTM recurrence (unchanged from R5).
//   warps 8-15 : xproj producer, tensor-core bf16 hi/lo split (3 passes),
//                128x128 tile per iteration, BK=16 double-buffered slabs.
// ---------------------------------------------------------------------------
extern __shared__ float smem_dyn[];

__global__ void __launch_bounds__(NTHR, 1)
lstm_fused_kernel(const float* __restrict__ embs,
                  const float* __restrict__ w_ih,
                  const float* __restrict__ w_hh,
                  const float* __restrict__ b_ih,
                  const float* __restrict__ b_hh,
                  const float* __restrict__ c0,
                  float* __restrict__ out) {
    float* w_s = smem_dyn;            // [1024][32] k-major, 128 KB
    float* hp  = smem_dyn + 32768;    // 32 KB staging/partials (recurrence)
    __nv_bfloat16* gx = (__nv_bfloat16*)(smem_dyn + 40960);  // 40 KB gemm bufs

    const int tid = threadIdx.x;
    const int blk = blockIdx.x;

    if (tid < 256) {
        // =================== RECURRENCE GROUP (warps 0-7) ===================
        const int c_base = blk * 8;
        {
            const int r    = tid & 31;
            const int kg   = tid >> 5;
            const int gate = r >> 3;
            const int cl   = r & 7;
            const float* wrow = w_hh + (size_t)(gate * KD + c_base + cl) * KD;
#pragma unroll 8
            for (int kk = 0; kk < 128; kk++) {
                int k = kg * 128 + kk;
                w_s[k * 32 + r] = wrow[k];
            }
        }

        const int warp  = tid >> 5;
        const int lane  = tid & 31;
        const int r_grp = lane >> 2;
        const int b_grp = lane & 3;
        float* my_stage = hp + warp * 1024;

        const int eb  = lane;
        const int ecl = warp;
        const int ec  = c_base + ecl;
        float c_state = c0[ec];

        NB_REC();
        if (tid == 0) {
            while (*(volatile unsigned*)&g_xflag[0] < 32u) { __nanosleep(64); }
        }
        NB_REC();
        __threadfence();

        for (int t = 0; t < TT; t++) {
            const float* hin  = g_hbuf[t & 1];
            float*       hout = g_hbuf[(t & 1) ^ 1];

            const float* xp = g_xproj + ((size_t)t * BB + eb) * GD + ec;
            float x_i = __ldcg(xp);
            float x_f = __ldcg(xp + KD);
            float x_g = __ldcg(xp + 2 * KD);
            float x_o = __ldcg(xp + 3 * KD);

            const float* hsrc = hin + warp * 128 * 32;
            float4 pf[4];
#pragma unroll
            for (int i = 0; i < 4; i++)
                pf[i] = __ldcg((const float4*)(hsrc + i * 128 + lane * 4));

            float acc[4][8];
#pragma unroll
            for (int ri = 0; ri < 4; ri++)
#pragma unroll
                for (int bi = 0; bi < 8; bi++) acc[ri][bi] = 0.f;

            for (int ch = 0; ch < 8; ch++) {
#pragma unroll
                for (int i = 0; i < 4; i++)
                    *(float4*)(my_stage + i * 128 + lane * 4) = pf[i];
                __syncwarp();
                if (ch < 7) {
#pragma unroll
                    for (int i = 0; i < 4; i++)
                        pf[i] = __ldcg((const float4*)(hsrc + (ch + 1) * 512 + i * 128 + lane * 4));
                }
                const float* wk = w_s + (warp * 128 + ch * 16) * 32;
#pragma unroll
                for (int kk = 0; kk < 16; kk++) {
                    float4 h0v = *(const float4*)(my_stage + kk * 32 + b_grp * 8);
                    float4 h1v = *(const float4*)(my_stage + kk * 32 + b_grp * 8 + 4);
                    float4 wv  = *(const float4*)(wk + kk * 32 + r_grp * 4);
                    float hv[8] = {h0v.x, h0v.y, h0v.z, h0v.w, h1v.x, h1v.y, h1v.z, h1v.w};
                    float wr[4] = {wv.x, wv.y, wv.z, wv.w};
#pragma unroll
                    for (int ri = 0; ri < 4; ri++)
#pragma unroll
                        for (int bi = 0; bi < 8; bi++)
                            acc[ri][bi] += wr[ri] * hv[bi];
                }
                __syncwarp();
            }

            NB_REC();
#pragma unroll
            for (int ri = 0; ri < 4; ri++) {
                int r = r_grp * 4 + ri;
                float4 p0 = make_float4(acc[ri][0], acc[ri][1], acc[ri][2], acc[ri][3]);
                float4 p1 = make_float4(acc[ri][4], acc[ri][5], acc[ri][6], acc[ri][7]);
                *(float4*)(hp + warp * 1024 + r * 32 + b_grp * 8)     = p0;
                *(float4*)(hp + warp * 1024 + r * 32 + b_grp * 8 + 4) = p1;
            }
            NB_REC();

            float gi = x_i, gf = x_f, gg = x_g, go = x_o;
#pragma unroll
            for (int j = 0; j < 8; j++) {
                const float* p = hp + j * 1024 + ecl * 32 + eb;
                gi += p[0 * 8 * 32];
                gf += p[1 * 8 * 32];
                gg += p[2 * 8 * 32];
                go += p[3 * 8 * 32];
            }
            float ig = 1.f / (1.f + __expf(-gi));
            float fg = 1.f / (1.f + __expf(-gf));
            float gt = tanhf(gg);
            float og = 1.f / (1.f + __expf(-go));
            c_state  = fg * c_state + ig * gt;
            float hn = og * tanhf(c_state);

            out[((size_t)t * BB + eb) * KD + ec] = hn;
            __stcg(&hout[ec * 32 + eb], hn);

            if (t != TT - 1) {
                __threadfence();
                NB_REC();
                if (tid == 0) {
                    atomicAdd(&g_bar_cnt, 1u);
                    unsigned target = (unsigned)(t + 1) * NBLK;
                    while (*(volatile unsigned*)&g_bar_cnt < target) {
                        __nanosleep(32);
                    }
                    unsigned ychunk = (unsigned)(t + 1) >> 2;
                    while (*(volatile unsigned*)&g_xflag[ychunk] < 32u) {
                        __nanosleep(32);
                    }
                }
                NB_REC();
                __threadfence();
            }
        }
    } else {
        // ============ XPROJ PRODUCER (warps 8-15): bf16-split HMMA ==========
        const int tid2 = tid - 256;
        const int x_b  = blk & 31;
        const int y_b  = blk >> 5;
        const int bn   = x_b * 128;

        const int wid2 = tid2 >> 5;       // 0..7
        const int lane = tid2 & 31;
        const int wm   = wid2 >> 2;       // 0..1  (m: 64 rows each)
        const int wn   = wid2 & 3;        // 0..3  (n: 32 cols each)
        const int g    = lane >> 2;       // 0..7
        const int tg   = lane & 3;        // 0..3

        // slab staging mapping: thread covers rows (tid2>>2) and +64, seg fixed
        const int srow = tid2 >> 2;       // 0..63
        const int seg  = tid2 & 3;        // float4 segment within 16-float row

        // per-thread bias for output columns
        float bias0[4], bias1[4];
#pragma unroll
        for (int nf = 0; nf < 4; nf++) {
            int cc = bn + wn * 32 + nf * 8 + 2 * tg;
            bias0[nf] = __ldg(&b_ih[cc])     + __ldg(&b_hh[cc]);
            bias1[nf] = __ldg(&b_ih[cc + 1]) + __ldg(&b_hh[cc + 1]);
        }

        // gemm smem: 2 stages, each: Ahi(2560) Alo(2560) Whi(2560) Wlo(2560) bf16
        __nv_bfloat16* stg[2] = { gx, gx + 10240 };

        const float4* Wg0 = (const float4*)(w_ih + (size_t)(bn + srow) * KD + seg * 4);
        const float4* Wg1 = (const float4*)(w_ih + (size_t)(bn + srow + 64) * KD + seg * 4);

        for (int it = 0; it < 32; it++) {
            const int y  = y_b + 4 * it;
            const int bm = y * 128;
            const float4* Ag0 = (const float4*)(embs + (size_t)(bm + srow) * KD + seg * 4);
            const float4* Ag1 = (const float4*)(embs + (size_t)(bm + srow + 64) * KD + seg * 4);

            float acc[4][4][4];
#pragma unroll
            for (int i = 0; i < 4; i++)
#pragma unroll
                for (int j = 0; j < 4; j++)
#pragma unroll
                    for (int q = 0; q < 4; q++) acc[i][j][q] = 0.f;

            // stage slab 0
            {
                float4 a0 = __ldg(Ag0), a1 = __ldg(Ag1);
                float4 w0 = __ldg(Wg0), w1 = __ldg(Wg1);
                __nv_bfloat16* Ahi = stg[0];
                __nv_bfloat16* Alo = stg[0] + 2560;
                __nv_bfloat16* Whi = stg[0] + 5120;
                __nv_bfloat16* Wlo = stg[0] + 7680;
                cvt_store_slab(Ahi, Alo, srow,      seg, a0);
                cvt_store_slab(Ahi, Alo, srow + 64, seg, a1);
                cvt_store_slab(Whi, Wlo, srow,      seg, w0);
                cvt_store_slab(Whi, Wlo, srow + 64, seg, w1);
            }
            NB_GEM();

            for (int s = 0; s < 64; s++) {
                float4 a0, a1, w0, w1;
                if (s < 63) {
                    a0 = __ldg(Ag0 + (s + 1) * 4);   // +16 floats = +4 float4
                    a1 = __ldg(Ag1 + (s + 1) * 4);
                    w0 = __ldg(Wg0 + (s + 1) * 4);
                    w1 = __ldg(Wg1 + (s + 1) * 4);
                }

                // compute slab s from stage s&1
                const __nv_bfloat16* base = stg[s & 1];
                const unsigned* Ahi = (const unsigned*)(base);
                const unsigned* Alo = (const unsigned*)(base + 2560);
                const unsigned* Whi = (const unsigned*)(base + 5120);
                const unsigned* Wlo = (const unsigned*)(base + 7680);

                // B fragments (hi & lo) for 4 n-frags
                unsigned bh[4][2], bl[4][2];
#pragma unroll
                for (int nf = 0; nf < 4; nf++) {
                    int nrow = wn * 32 + nf * 8 + g;   // word stride 10 per row
                    bh[nf][0] = Whi[nrow * 10 + tg];
                    bh[nf][1] = Whi[nrow * 10 + tg + 4];
                    bl[nf][0] = Wlo[nrow * 10 + tg];
                    bl[nf][1] = Wlo[nrow * 10 + tg + 4];
                }
#pragma unroll
                for (int mf = 0; mf < 4; mf++) {
                    int ar = (wm * 64 + mf * 16 + g) * 10;  // word index
                    unsigned a0f = Ahi[ar + tg];
                    unsigned a1f = Ahi[ar + 80 + tg];
                    unsigned a2f = Ahi[ar + tg + 4];
                    unsigned a3f = Ahi[ar + 80 + tg + 4];
#pragma unroll
                    for (int nf = 0; nf < 4; nf++) {
                        mma16816(acc[mf][nf], a0f, a1f, a2f, a3f, bh[nf][0], bh[nf][1]);
                        mma16816(acc[mf][nf], a0f, a1f, a2f, a3f, bl[nf][0], bl[nf][1]);
                    }
                }
#pragma unroll
                for (int mf = 0; mf < 4; mf++) {
                    int ar = (wm * 64 + mf * 16 + g) * 10;
                    unsigned a0f = Alo[ar + tg];
                    unsigned a1f = Alo[ar + 80 + tg];
                    unsigned a2f = Alo[ar + tg + 4];
                    unsigned a3f = Alo[ar + 80 + tg + 4];
#pragma unroll
                    for (int nf = 0; nf < 4; nf++) {
                        mma16816(acc[mf][nf], a0f, a1f, a2f, a3f, bh[nf][0], bh[nf][1]);
                    }
                }

                if (s < 63) {
                    __nv_bfloat16* nb = stg[(s + 1) & 1];
                    cvt_store_slab(nb,        nb + 2560, srow,      seg, a0);
                    cvt_store_slab(nb,        nb + 2560, srow + 64, seg, a1);
                    cvt_store_slab(nb + 5120, nb + 7680, srow,      seg, w0);
                    cvt_store_slab(nb + 5120, nb + 7680, srow + 64, seg, w1);
                }
                NB_GEM();
            }

            // epilogue: bias + store tile to g_xproj
#pragma unroll
            for (int mf = 0; mf < 4; mf++) {
                int r0 = bm + wm * 64 + mf * 16 + g;
#pragma unroll
                for (int nf = 0; nf < 4; nf++) {
                    int cc = bn + wn * 32 + nf * 8 + 2 * tg;
                    float2 v0, v1;
                    v0.x = acc[mf][nf][0] + bias0[nf];
                    v0.y = acc[mf][nf][1] + bias1[nf];
                    v1.x = acc[mf][nf][2] + bias0[nf];
                    v1.y = acc[mf][nf][3] + bias1[nf];
                    __stcg((float2*)&g_xproj[(size_t)r0 * GD + cc], v0);
                    __stcg((float2*)&g_xproj[(size_t)(r0 + 8) * GD + cc], v1);
                }
            }

            __threadfence();
            NB_GEM();
            if (tid2 == 0) atomicAdd(&g_xflag[y], 1u);
        }
    }
}

// ---------------------------------------------------------------------------
extern "C" void kernel_launch(void* const* d_in, const int* in_sizes, int n_in,
                              void* d_out, int out_size) {
    const float* embs = (const float*)d_in[0];
    const float* w_ih = (const float*)d_in[1];
    const float* w_hh = (const float*)d_in[2];
    const float* b_ih = (const float*)d_in[3];
    const float* b_hh = (const float*)d_in[4];
    const float* h0   = (const float*)d_in[5];
    const float* c0   = (const float*)d_in[6];
    float* out = (float*)d_out;

    init_state_kernel<<<128, 256>>>(h0);

    static int smem_set = 0;
    const int smem_bytes = (40960 + 10240) * (int)sizeof(float);  // 200 KB
    if (!smem_set) {
        cudaFuncSetAttribute(lstm_fused_kernel,
                             cudaFuncAttributeMaxDynamicSharedMemorySize,
                             smem_bytes);
        smem_set = 1;
    }
    lstm_fused_kernel<<<NBLK, NTHR, smem_bytes>>>(embs, w_ih, w_hh, b_ih, b_hh,
                                                  c0, out);
}

// round 7
// speedup vs baseline: 1.2089x; 1.0369x over previous
#include <cuda_runtime.h>
#include <cuda_bf16.h>
#include <math.h>

#define TT 512
#define BB 32
#define KD 1024
#define GD 4096
#define NBLK 128
#define NTHR 512

// Scratch
__device__ float g_xproj[(size_t)TT * BB * GD];
__device__ __align__(32) __nv_bfloat16 g_hhi[2][BB * KD];   // [b][k]
__device__ __align__(32) __nv_bfloat16 g_hlo[2][BB * KD];   // [b][k]
__device__ unsigned g_bar_cnt;
__device__ unsigned g_xflag[128];

#define NB_REC() asm volatile("bar.sync 1, 256;" ::: "memory")
#define NB_GEM() asm volatile("bar.sync 2, 256;" ::: "memory")

// smem word offsets
#define WFH_OFF 0          // W frags hi: 16384 words (64 KB)
#define WFL_OFF 16384      // W frags lo: 16384 words
#define HP_OFF  32768      // partials: 4 bufs x 32x34 = 4352 words
#define HCH_OFF 37120      // h chunks: 2 stages x (hi 2176 + lo 2176) = 8704 words
#define GX_OFF  45824      // producer: 10240 words (40 KB)
#define SMEM_WORDS 56064   // 224256 bytes

// ---------------------------------------------------------------------------
__global__ void init_state_kernel(const float* __restrict__ h0) {
    int i = blockIdx.x * blockDim.x + threadIdx.x;   // 0..32767 = b*1024 + k
    int k = i & 1023;
    float v = h0[k];
    __nv_bfloat16 hb = __float2bfloat16_rn(v);
    g_hhi[0][i] = hb;
    g_hlo[0][i] = __float2bfloat16_rn(v - __bfloat162float(hb));
    if (i == 0) g_bar_cnt = 0u;
    if (i < 128) g_xflag[i] = 0u;
}

// ---------------------------------------------------------------------------
__device__ __forceinline__ void mma16816(float* c,
                                         unsigned a0, unsigned a1, unsigned a2, unsigned a3,
                                         unsigned b0, unsigned b1) {
    asm volatile(
        "mma.sync.aligned.m16n8k16.row.col.f32.bf16.bf16.f32 "
        "{%0,%1,%2,%3}, {%4,%5,%6,%7}, {%8,%9}, {%0,%1,%2,%3};\n"
        : "+f"(c[0]), "+f"(c[1]), "+f"(c[2]), "+f"(c[3])
        : "r"(a0), "r"(a1), "r"(a2), "r"(a3), "r"(b0), "r"(b1));
}

__device__ __forceinline__ void split2(float x, float y, unsigned& h, unsigned& l) {
    __nv_bfloat16 bx = __float2bfloat16_rn(x);
    __nv_bfloat16 by = __float2bfloat16_rn(y);
    __nv_bfloat162 hv; hv.x = bx; hv.y = by;
    h = *(unsigned*)&hv;
    __nv_bfloat162 lv = __floats2bfloat162_rn(x - __bfloat162float(bx),
                                              y - __bfloat162float(by));
    l = *(unsigned*)&lv;
}

// convert float4 -> hi/lo bf16 and store into padded smem slab [128][20] (producer)
__device__ __forceinline__ void cvt_store_slab(__nv_bfloat16* hi, __nv_bfloat16* lo,
                                               int row, int seg, float4 v) {
    int idx = row * 20 + seg * 4;
    __nv_bfloat16 hx = __float2bfloat16_rn(v.x);
    __nv_bfloat16 hy = __float2bfloat16_rn(v.y);
    __nv_bfloat16 hz = __float2bfloat16_rn(v.z);
    __nv_bfloat16 hw = __float2bfloat16_rn(v.w);
    float lx = v.x - __bfloat162float(hx);
    float ly = v.y - __bfloat162float(hy);
    float lz = v.z - __bfloat162float(hz);
    float lw = v.w - __bfloat162float(hw);
    __nv_bfloat162 h01; h01.x = hx; h01.y = hy;
    __nv_bfloat162 h23; h23.x = hz; h23.y = hw;
    *(__nv_bfloat162*)&hi[idx]     = h01;
    *(__nv_bfloat162*)&hi[idx + 2] = h23;
    *(__nv_bfloat162*)&lo[idx]     = __floats2bfloat162_rn(lx, ly);
    *(__nv_bfloat162*)&lo[idx + 2] = __floats2bfloat162_rn(lz, lw);
}

// ---------------------------------------------------------------------------
extern __shared__ float smem_dyn[];

__global__ void __launch_bounds__(NTHR, 1)
lstm_fused_kernel(const float* __restrict__ embs,
                  const float* __restrict__ w_ih,
                  const float* __restrict__ w_hh,
                  const float* __restrict__ b_ih,
                  const float* __restrict__ b_hh,
                  const float* __restrict__ c0,
                  float* __restrict__ out) {
    unsigned* wfH = (unsigned*)smem_dyn + WFH_OFF;
    unsigned* wfL = (unsigned*)smem_dyn + WFL_OFF;
    float*    hp  = smem_dyn + HP_OFF;
    unsigned* hch = (unsigned*)smem_dyn + HCH_OFF;
    __nv_bfloat16* gx = (__nv_bfloat16*)(smem_dyn + GX_OFF);

    const int tid = threadIdx.x;
    const int blk = blockIdx.x;

    if (tid < 256) {
        // =============== RECURRENCE GROUP (warps 0-7, tensor core) ==========
        const int c_base = blk * 8;
        const int w    = tid >> 5;
        const int lane = tid & 31;
        const int g    = lane >> 2;
        const int tg   = lane & 3;

        // ---- pre-pack W fragments (hi/lo) into smem, mma-ready layout ----
        for (int c = 0; c < 8; c++) {
            int ks = c * 8 + w;
            int k0 = c * 128 + w * 16 + 2 * tg;
#pragma unroll
            for (int mt = 0; mt < 2; mt++) {
                int r0 = mt * 16 + g;          // D row (gate*8+cl), rows r0, r0+8
                int r1 = r0 + 8;
                const float* row0 = w_hh + (size_t)((r0 >> 3) * KD + c_base + (r0 & 7)) * KD;
                const float* row1 = w_hh + (size_t)((r1 >> 3) * KD + c_base + (r1 & 7)) * KD;
                unsigned h0, h1, h2, h3, l0, l1, l2, l3;
                split2(row0[k0],     row0[k0 + 1], h0, l0);
                split2(row1[k0],     row1[k0 + 1], h1, l1);
                split2(row0[k0 + 8], row0[k0 + 9], h2, l2);
                split2(row1[k0 + 8], row1[k0 + 9], h3, l3);
                int off = (ks * 2 + mt) * 128 + lane * 4;
                *(uint4*)(wfH + off) = make_uint4(h0, h1, h2, h3);
                *(uint4*)(wfL + off) = make_uint4(l0, l1, l2, l3);
            }
        }

        const int eb = lane;            // batch
        const int ec = c_base + w;      // cell index
        float c_state = c0[ec];
        const int sb  = tid >> 3;       // staging: row b
        const int sg_ = tid & 7;        // staging: 32B segment

        NB_REC();
        if (tid == 0) {
            while (((volatile unsigned*)g_xflag)[0] < 32u) { __nanosleep(64); }
        }
        NB_REC();
        __threadfence();

        for (int t = 0; t < TT; t++) {
            const __nv_bfloat16* hH = g_hhi[t & 1];
            const __nv_bfloat16* hL = g_hlo[t & 1];
            const int np = (t & 1) ^ 1;

            // chunk-0 global loads first (critical path)
            uint4 ph0, ph1, pl0, pl1;
            {
                const uint4* pH = (const uint4*)(hH + sb * KD + sg_ * 16);
                const uint4* pL = (const uint4*)(hL + sb * KD + sg_ * 16);
                ph0 = __ldcg(pH); ph1 = __ldcg(pH + 1);
                pl0 = __ldcg(pL); pl1 = __ldcg(pL + 1);
            }
            // x prefetch
            const float* xp = g_xproj + ((size_t)t * BB + eb) * GD + ec;
            float x_i = __ldcg(xp);
            float x_f = __ldcg(xp + KD);
            float x_g = __ldcg(xp + 2 * KD);
            float x_o = __ldcg(xp + 3 * KD);
            // stage chunk 0
            {
                unsigned* d = hch + sb * 68 + sg_ * 8;
                *(uint4*)d = ph0; *(uint4*)(d + 4) = ph1;
                *(uint4*)(d + 2176) = pl0; *(uint4*)(d + 2180) = pl1;
            }
            NB_REC();

            float acc[2][4][4];
#pragma unroll
            for (int mt = 0; mt < 2; mt++)
#pragma unroll
                for (int nt = 0; nt < 4; nt++)
#pragma unroll
                    for (int q = 0; q < 4; q++) acc[mt][nt][q] = 0.f;

            for (int c = 0; c < 8; c++) {
                if (c < 7) {
                    const uint4* pH = (const uint4*)(hH + sb * KD + (c + 1) * 128 + sg_ * 16);
                    const uint4* pL = (const uint4*)(hL + sb * KD + (c + 1) * 128 + sg_ * 16);
                    ph0 = __ldcg(pH); ph1 = __ldcg(pH + 1);
                    pl0 = __ldcg(pL); pl1 = __ldcg(pL + 1);
                }
                int ks = c * 8 + w;
                uint4 AH0 = *(const uint4*)(wfH + (ks * 2 + 0) * 128 + lane * 4);
                uint4 AH1 = *(const uint4*)(wfH + (ks * 2 + 1) * 128 + lane * 4);
                uint4 AL0 = *(const uint4*)(wfL + (ks * 2 + 0) * 128 + lane * 4);
                uint4 AL1 = *(const uint4*)(wfL + (ks * 2 + 1) * 128 + lane * 4);
                const unsigned* bhb = hch + (c & 1) * 4352;
                const unsigned* blb = bhb + 2176;
                const int kk = w * 8 + tg;
#pragma unroll
                for (int nt = 0; nt < 4; nt++) {
                    int bi = (nt * 8 + g) * 68 + kk;
                    unsigned bh0 = bhb[bi], bh1 = bhb[bi + 4];
                    unsigned bl0 = blb[bi], bl1 = blb[bi + 4];
                    mma16816(acc[0][nt], AH0.x, AH0.y, AH0.z, AH0.w, bh0, bh1);
                    mma16816(acc[1][nt], AH1.x, AH1.y, AH1.z, AH1.w, bh0, bh1);
                    mma16816(acc[0][nt], AH0.x, AH0.y, AH0.z, AH0.w, bl0, bl1);
                    mma16816(acc[1][nt], AH1.x, AH1.y, AH1.z, AH1.w, bl0, bl1);
                    mma16816(acc[0][nt], AL0.x, AL0.y, AL0.z, AL0.w, bh0, bh1);
                    mma16816(acc[1][nt], AL1.x, AL1.y, AL1.z, AL1.w, bh0, bh1);
                }
                if (c < 7) {
                    unsigned* d = hch + ((c + 1) & 1) * 4352 + sb * 68 + sg_ * 8;
                    *(uint4*)d = ph0; *(uint4*)(d + 4) = ph1;
                    *(uint4*)(d + 2176) = pl0; *(uint4*)(d + 2180) = pl1;
                }
                NB_REC();
            }

            // ---- 2-round partial reduction in smem ----
            if (w >= 4) {
                float* buf = hp + (w - 4) * 1088;
#pragma unroll
                for (int mt = 0; mt < 2; mt++)
#pragma unroll
                    for (int nt = 0; nt < 4; nt++) {
                        int r0 = mt * 16 + g, col = nt * 8 + 2 * tg;
                        *(float2*)&buf[r0 * 34 + col] =
                            make_float2(acc[mt][nt][0], acc[mt][nt][1]);
                        *(float2*)&buf[(r0 + 8) * 34 + col] =
                            make_float2(acc[mt][nt][2], acc[mt][nt][3]);
                    }
            }
            NB_REC();
            if (w < 4) {
                float* buf = hp + w * 1088;
#pragma unroll
                for (int mt = 0; mt < 2; mt++)
#pragma unroll
                    for (int nt = 0; nt < 4; nt++) {
                        int r0 = mt * 16 + g, col = nt * 8 + 2 * tg;
                        float2 p0 = *(float2*)&buf[r0 * 34 + col];
                        float2 p1 = *(float2*)&buf[(r0 + 8) * 34 + col];
                        p0.x += acc[mt][nt][0]; p0.y += acc[mt][nt][1];
                        p1.x += acc[mt][nt][2]; p1.y += acc[mt][nt][3];
                        *(float2*)&buf[r0 * 34 + col] = p0;
                        *(float2*)&buf[(r0 + 8) * 34 + col] = p1;
                    }
            }
            NB_REC();

            // ---- fused gate epilogue: thread = (cl=w, b=eb) ----
            float gv[4];
#pragma unroll
            for (int gate = 0; gate < 4; gate++) {
                int ro = (gate * 8 + w) * 34 + eb;
                gv[gate] = hp[ro] + hp[1088 + ro] + hp[2176 + ro] + hp[3264 + ro];
            }
            float gi = x_i + gv[0], gf = x_f + gv[1];
            float gg = x_g + gv[2], go = x_o + gv[3];
            float ig = 1.f / (1.f + __expf(-gi));
            float fg = 1.f / (1.f + __expf(-gf));
            float gt = tanhf(gg);
            float og = 1.f / (1.f + __expf(-go));
            c_state  = fg * c_state + ig * gt;
            float hn = og * tanhf(c_state);

            out[((size_t)t * BB + eb) * KD + ec] = hn;
            __nv_bfloat16 hb = __float2bfloat16_rn(hn);
            __nv_bfloat16 lb = __float2bfloat16_rn(hn - __bfloat162float(hb));
            unsigned short hus = *(unsigned short*)&hb;
            unsigned short lus = *(unsigned short*)&lb;
            asm volatile("st.global.cg.u16 [%0], %1;"
                         :: "l"(&g_hhi[np][eb * KD + ec]), "h"(hus));
            asm volatile("st.global.cg.u16 [%0], %1;"
                         :: "l"(&g_hlo[np][eb * KD + ec]), "h"(lus));

            // ---- inter-block barrier + next-step xproj-ready wait ----
            if (t != TT - 1) {
                __threadfence();
                NB_REC();
                if (tid == 0) {
                    atomicAdd(&g_bar_cnt, 1u);
                    unsigned target = (unsigned)(t + 1) * NBLK;
                    while (*(volatile unsigned*)&g_bar_cnt < target) {
                        __nanosleep(32);
                    }
                    unsigned ychunk = (unsigned)(t + 1) >> 2;
                    while (*(volatile unsigned*)&g_xflag[ychunk] < 32u) {
                        __nanosleep(32);
                    }
                }
                NB_REC();
                __threadfence();
            }
        }
    } else {
        // ============ XPROJ PRODUCER (warps 8-15): bf16-split HMMA ==========
        const int tid2 = tid - 256;
        const int x_b  = blk & 31;
        const int y_b  = blk >> 5;
        const int bn   = x_b * 128;

        const int wid2 = tid2 >> 5;
        const int lane = tid2 & 31;
        const int wm   = wid2 >> 2;
        const int wn   = wid2 & 3;
        const int g    = lane >> 2;
        const int tg   = lane & 3;

        const int srow = tid2 >> 2;
        const int seg  = tid2 & 3;

        float bias0[4], bias1[4];
#pragma unroll
        for (int nf = 0; nf < 4; nf++) {
            int cc = bn + wn * 32 + nf * 8 + 2 * tg;
            bias0[nf] = __ldg(&b_ih[cc])     + __ldg(&b_hh[cc]);
            bias1[nf] = __ldg(&b_ih[cc + 1]) + __ldg(&b_hh[cc + 1]);
        }

        __nv_bfloat16* stg[2] = { gx, gx + 10240 };

        const float4* Wg0 = (const float4*)(w_ih + (size_t)(bn + srow) * KD + seg * 4);
        const float4* Wg1 = (const float4*)(w_ih + (size_t)(bn + srow + 64) * KD + seg * 4);

        for (int it = 0; it < 32; it++) {
            const int y  = y_b + 4 * it;
            const int bm = y * 128;
            const float4* Ag0 = (const float4*)(embs + (size_t)(bm + srow) * KD + seg * 4);
            const float4* Ag1 = (const float4*)(embs + (size_t)(bm + srow + 64) * KD + seg * 4);

            float acc[4][4][4];
#pragma unroll
            for (int i = 0; i < 4; i++)
#pragma unroll
                for (int j = 0; j < 4; j++)
#pragma unroll
                    for (int q = 0; q < 4; q++) acc[i][j][q] = 0.f;

            {
                float4 a0 = __ldg(Ag0), a1 = __ldg(Ag1);
                float4 w0 = __ldg(Wg0), w1 = __ldg(Wg1);
                __nv_bfloat16* Ahi = stg[0];
                __nv_bfloat16* Alo = stg[0] + 2560;
                __nv_bfloat16* Whi = stg[0] + 5120;
                __nv_bfloat16* Wlo = stg[0] + 7680;
                cvt_store_slab(Ahi, Alo, srow,      seg, a0);
                cvt_store_slab(Ahi, Alo, srow + 64, seg, a1);
                cvt_store_slab(Whi, Wlo, srow,      seg, w0);
                cvt_store_slab(Whi, Wlo, srow + 64, seg, w1);
            }
            NB_GEM();

            for (int s = 0; s < 64; s++) {
                float4 a0, a1, w0, w1;
                if (s < 63) {
                    a0 = __ldg(Ag0 + (s + 1) * 4);
                    a1 = __ldg(Ag1 + (s + 1) * 4);
                    w0 = __ldg(Wg0 + (s + 1) * 4);
                    w1 = __ldg(Wg1 + (s + 1) * 4);
                }

                const __nv_bfloat16* base = stg[s & 1];
                const unsigned* Ahi = (const unsigned*)(base);
                const unsigned* Alo = (const unsigned*)(base + 2560);
                const unsigned* Whi = (const unsigned*)(base + 5120);
                const unsigned* Wlo = (const unsigned*)(base + 7680);

                unsigned bh[4][2], bl[4][2];
#pragma unroll
                for (int nf = 0; nf < 4; nf++) {
                    int nrow = wn * 32 + nf * 8 + g;
                    bh[nf][0] = Whi[nrow * 10 + tg];
                    bh[nf][1] = Whi[nrow * 10 + tg + 4];
                    bl[nf][0] = Wlo[nrow * 10 + tg];
                    bl[nf][1] = Wlo[nrow * 10 + tg + 4];
                }
#pragma unroll
                for (int mf = 0; mf < 4; mf++) {
                    int ar = (wm * 64 + mf * 16 + g) * 10;
                    unsigned a0f = Ahi[ar + tg];
                    unsigned a1f = Ahi[ar + 80 + tg];
                    unsigned a2f = Ahi[ar + tg + 4];
                    unsigned a3f = Ahi[ar + 80 + tg + 4];
#pragma unroll
                    for (int nf = 0; nf < 4; nf++) {
                        mma16816(acc[mf][nf], a0f, a1f, a2f, a3f, bh[nf][0], bh[nf][1]);
                        mma16816(acc[mf][nf], a0f, a1f, a2f, a3f, bl[nf][0], bl[nf][1]);
                    }
                }
#pragma unroll
                for (int mf = 0; mf < 4; mf++) {
                    int ar = (wm * 64 + mf * 16 + g) * 10;
                    unsigned a0f = Alo[ar + tg];
                    unsigned a1f = Alo[ar + 80 + tg];
                    unsigned a2f = Alo[ar + tg + 4];
                    unsigned a3f = Alo[ar + 80 + tg + 4];
#pragma unroll
                    for (int nf = 0; nf < 4; nf++) {
                        mma16816(acc[mf][nf], a0f, a1f, a2f, a3f, bh[nf][0], bh[nf][1]);
                    }
                }

                if (s < 63) {
                    __nv_bfloat16* nb = stg[(s + 1) & 1];
                    cvt_store_slab(nb,        nb + 2560, srow,      seg, a0);
                    cvt_store_slab(nb,        nb + 2560, srow + 64, seg, a1);
                    cvt_store_slab(nb + 5120, nb + 7680, srow,      seg, w0);
                    cvt_store_slab(nb + 5120, nb + 7680, srow + 64, seg, w1);
                }
                NB_GEM();
            }

#pragma unroll
            for (int mf = 0; mf < 4; mf++) {
                int r0 = bm + wm * 64 + mf * 16 + g;
#pragma unroll
                for (int nf = 0; nf < 4; nf++) {
                    int cc = bn + wn * 32 + nf * 8 + 2 * tg;
                    float2 v0, v1;
                    v0.x = acc[mf][nf][0] + bias0[nf];
                    v0.y = acc[mf][nf][1] + bias1[nf];
                    v1.x = acc[mf][nf][2] + bias0[nf];
                    v1.y = acc[mf][nf][3] + bias1[nf];
                    __stcg((float2*)&g_xproj[(size_t)r0 * GD + cc], v0);
                    __stcg((float2*)&g_xproj[(size_t)(r0 + 8) * GD + cc], v1);
                }
            }

            __threadfence();
            NB_GEM();
            if (tid2 == 0) atomicAdd(&g_xflag[y], 1u);
        }
    }
}

// ---------------------------------------------------------------------------
extern "C" void kernel_launch(void* const* d_in, const int* in_sizes, int n_in,
                              void* d_out, int out_size) {
    const float* embs = (const float*)d_in[0];
    const float* w_ih = (const float*)d_in[1];
    const float* w_hh = (const float*)d_in[2];
    const float* b_ih = (const float*)d_in[3];
    const float* b_hh = (const float*)d_in[4];
    const float* h0   = (const float*)d_in[5];
    const float* c0   = (const float*)d_in[6];
    float* out = (float*)d_out;

    init_state_kernel<<<128, 256>>>(h0);

    static int smem_set = 0;
    const int smem_bytes = SMEM_WORDS * (int)sizeof(float);  // 224256 B
    if (!smem_set) {
        cudaFuncSetAttribute(lstm_fused_kernel,
                             cudaFuncAttributeMaxDynamicSharedMemorySize,
                             smem_bytes);
        smem_set = 1;
    }
    lstm_fused_kernel<<<NBLK, NTHR, smem_bytes>>>(embs, w_ih, w_hh, b_ih, b_hh,
                                                  c0, out);
}

// round 8
// speedup vs baseline: 1.2426x; 1.0279x over previous
#include <cuda_runtime.h>
#include <cuda_bf16.h>
#include <math.h>

#define TT 512
#define BB 32
#define KD 1024
#define GD 4096
#define NBLK 128
#define NTHR 512

// Scratch
__device__ float g_xproj[(size_t)TT * BB * GD];
__device__ __align__(16) unsigned g_hpk[2][KD * BB];   // [k][b], hi|lo<<16 packed bf16
__device__ unsigned g_ckcnt[8];     // per chunk-group step-completion counters
__device__ unsigned g_xflag[128];   // y-chunk -> # n-tiles finished (target 32)

#define NB_REC() asm volatile("bar.sync 1, 256;" ::: "memory")
#define NB_GEM() asm volatile("bar.sync 2, 256;" ::: "memory")

// smem word offsets (4B words)
#define WFH_OFF 0          // W frags hi: 16384 words (64 KB)
#define WFL_OFF 16384      // W frags lo: 16384 words (64 KB)
#define HP_OFF  32768      // partials: 4 bufs x 32x34 = 4352 words (17 KB)
#define HST_OFF 37120      // h stage: 2 x 128x36 uints = 9216 words (36 KB)
#define GX_OFF  46336      // producer: 10240 words (40 KB)
#define SMEM_WORDS 56576   // 226304 B

// ---------------------------------------------------------------------------
__global__ void init_state_kernel(const float* __restrict__ h0) {
    int i = blockIdx.x * blockDim.x + threadIdx.x;   // 0..32767 = k*32 + b
    int k = i >> 5;
    float v = h0[k];
    __nv_bfloat16 hb = __float2bfloat16_rn(v);
    __nv_bfloat16 lb = __float2bfloat16_rn(v - __bfloat162float(hb));
    g_hpk[0][i] = (unsigned)*(unsigned short*)&hb |
                  ((unsigned)*(unsigned short*)&lb << 16);
    if (i < 8) g_ckcnt[i] = 0u;
    if (i < 128) g_xflag[i] = 0u;
}

// ---------------------------------------------------------------------------
__device__ __forceinline__ void mma16816(float* c,
                                         unsigned a0, unsigned a1, unsigned a2, unsigned a3,
                                         unsigned b0, unsigned b1) {
    asm volatile(
        "mma.sync.aligned.m16n8k16.row.col.f32.bf16.bf16.f32 "
        "{%0,%1,%2,%3}, {%4,%5,%6,%7}, {%8,%9}, {%0,%1,%2,%3};\n"
        : "+f"(c[0]), "+f"(c[1]), "+f"(c[2]), "+f"(c[3])
        : "r"(a0), "r"(a1), "r"(a2), "r"(a3), "r"(b0), "r"(b1));
}

__device__ __forceinline__ void split2(float x, float y, unsigned& h, unsigned& l) {
    __nv_bfloat16 bx = __float2bfloat16_rn(x);
    __nv_bfloat16 by = __float2bfloat16_rn(y);
    __nv_bfloat162 hv; hv.x = bx; hv.y = by;
    h = *(unsigned*)&hv;
    __nv_bfloat162 lv = __floats2bfloat162_rn(x - __bfloat162float(bx),
                                              y - __bfloat162float(by));
    l = *(unsigned*)&lv;
}

__device__ __forceinline__ unsigned ld_acq(const unsigned* p) {
    unsigned v;
    asm volatile("ld.acquire.gpu.global.u32 %0, [%1];" : "=r"(v) : "l"(p) : "memory");
    return v;
}
__device__ __forceinline__ void red_rel(unsigned* p, unsigned v) {
    asm volatile("red.release.gpu.global.add.u32 [%0], %1;" :: "l"(p), "r"(v) : "memory");
}

// producer slab conversion (unchanged from R7)
__device__ __forceinline__ void cvt_store_slab(__nv_bfloat16* hi, __nv_bfloat16* lo,
                                               int row, int seg, float4 v) {
    int idx = row * 20 + seg * 4;
    __nv_bfloat16 hx = __float2bfloat16_rn(v.x);
    __nv_bfloat16 hy = __float2bfloat16_rn(v.y);
    __nv_bfloat16 hz = __float2bfloat16_rn(v.z);
    __nv_bfloat16 hw = __float2bfloat16_rn(v.w);
    float lx = v.x - __bfloat162float(hx);
    float ly = v.y - __bfloat162float(hy);
    float lz = v.z - __bfloat162float(hz);
    float lw = v.w - __bfloat162float(hw);
    __nv_bfloat162 h01; h01.x = hx; h01.y = hy;
    __nv_bfloat162 h23; h23.x = hz; h23.y = hw;
    *(__nv_bfloat162*)&hi[idx]     = h01;
    *(__nv_bfloat162*)&hi[idx + 2] = h23;
    *(__nv_bfloat162*)&lo[idx]     = __floats2bfloat162_rn(lx, ly);
    *(__nv_bfloat162*)&lo[idx + 2] = __floats2bfloat162_rn(lz, lw);
}

// ---------------------------------------------------------------------------
extern __shared__ float smem_dyn[];

__global__ void __launch_bounds__(NTHR, 1)
lstm_fused_kernel(const float* __restrict__ embs,
                  const float* __restrict__ w_ih,
                  const float* __restrict__ w_hh,
                  const float* __restrict__ b_ih,
                  const float* __restrict__ b_hh,
                  const float* __restrict__ c0,
                  float* __restrict__ out) {
    unsigned* wfH = (unsigned*)smem_dyn + WFH_OFF;
    unsigned* wfL = (unsigned*)smem_dyn + WFL_OFF;
    float*    hp  = smem_dyn + HP_OFF;
    unsigned* hst = (unsigned*)smem_dyn + HST_OFF;
    __nv_bfloat16* gx = (__nv_bfloat16*)((unsigned*)smem_dyn + GX_OFF);

    const int tid = threadIdx.x;
    const int blk = blockIdx.x;

    if (tid < 256) {
        // =============== RECURRENCE GROUP (warps 0-7, tensor core) ==========
        const int c_base = blk * 8;
        const int w    = tid >> 5;
        const int lane = tid & 31;
        const int g    = lane >> 2;
        const int tg   = lane & 3;
        const int mygrp = blk >> 4;

        // ---- pre-pack W fragments (hi/lo) into smem, mma-ready layout ----
        for (int c = 0; c < 8; c++) {
            int ks = c * 8 + w;
            int k0 = c * 128 + w * 16 + 2 * tg;
#pragma unroll
            for (int mt = 0; mt < 2; mt++) {
                int r0 = mt * 16 + g;
                int r1 = r0 + 8;
                const float* row0 = w_hh + (size_t)((r0 >> 3) * KD + c_base + (r0 & 7)) * KD;
                const float* row1 = w_hh + (size_t)((r1 >> 3) * KD + c_base + (r1 & 7)) * KD;
                unsigned h0, h1, h2, h3, l0, l1, l2, l3;
                split2(row0[k0],     row0[k0 + 1], h0, l0);
                split2(row1[k0],     row1[k0 + 1], h1, l1);
                split2(row0[k0 + 8], row0[k0 + 9], h2, l2);
                split2(row1[k0 + 8], row1[k0 + 9], h3, l3);
                int off = (ks * 2 + mt) * 128 + lane * 4;
                *(uint4*)(wfH + off) = make_uint4(h0, h1, h2, h3);
                *(uint4*)(wfL + off) = make_uint4(l0, l1, l2, l3);
            }
        }

        const int eb = lane;            // batch
        const int ec = c_base + w;      // cell index
        float c_state = c0[ec];
        const int krow = tid >> 1;      // staging: k row 0..127
        const int half = tid & 1;       // staging: b half (0-15 / 16-31)

        NB_REC();

        for (int t = 0; t < TT; t++) {
            const unsigned* hin = g_hpk[t & 1];
            unsigned*      hout = g_hpk[(t & 1) ^ 1];

            // ---- step-start wait: h of step t-1 + xproj chunk ready ----
            {
                unsigned tgt = 16u * (unsigned)t;
                const unsigned* cp = &g_ckcnt[lane & 7];
                const unsigned* xp_ = &g_xflag[t >> 2];
                while (true) {
                    unsigned v  = ld_acq(cp);
                    unsigned xv = ld_acq(xp_);
                    if (__all_sync(0xffffffffu, (v >= tgt) & (xv >= 32u))) break;
                    __nanosleep(32);
                }
            }

            // ---- chunk-0 global loads (critical path) ----
            uint4 pv0, pv1, pv2, pv3;
            {
                const uint4* src = (const uint4*)(hin + krow * 32 + half * 16);
                pv0 = __ldcg(src); pv1 = __ldcg(src + 1);
                pv2 = __ldcg(src + 2); pv3 = __ldcg(src + 3);
            }
            // x prefetch
            const float* xq = g_xproj + ((size_t)t * BB + eb) * GD + ec;
            float x_i = __ldcg(xq);
            float x_f = __ldcg(xq + KD);
            float x_g = __ldcg(xq + 2 * KD);
            float x_o = __ldcg(xq + 3 * KD);
            // stage chunk 0
            {
                uint4* d = (uint4*)(hst + krow * 36 + half * 16);
                d[0] = pv0; d[1] = pv1; d[2] = pv2; d[3] = pv3;
            }
            NB_REC();

            float acc[2][4][4];
#pragma unroll
            for (int mt = 0; mt < 2; mt++)
#pragma unroll
                for (int nt = 0; nt < 4; nt++)
#pragma unroll
                    for (int q = 0; q < 4; q++) acc[mt][nt][q] = 0.f;

            const int kk = w * 8 + tg;
            for (int c = 0; c < 8; c++) {
                if (c < 7) {
                    const uint4* src = (const uint4*)(hin + (c + 1) * 128 * 32 +
                                                      krow * 32 + half * 16);
                    pv0 = __ldcg(src); pv1 = __ldcg(src + 1);
                    pv2 = __ldcg(src + 2); pv3 = __ldcg(src + 3);
                }
                int ks = c * 8 + w;
                uint4 AH0 = *(const uint4*)(wfH + (ks * 2 + 0) * 128 + lane * 4);
                uint4 AH1 = *(const uint4*)(wfH + (ks * 2 + 1) * 128 + lane * 4);
                uint4 AL0 = *(const uint4*)(wfL + (ks * 2 + 0) * 128 + lane * 4);
                uint4 AL1 = *(const uint4*)(wfL + (ks * 2 + 1) * 128 + lane * 4);
                const unsigned* sb = hst + (c & 1) * 4608;
#pragma unroll
                for (int nt = 0; nt < 4; nt++) {
                    const unsigned* p0 = sb + (2 * kk) * 36 + nt * 8 + g;
                    unsigned u00 = p0[0],   u01 = p0[36];
                    unsigned u10 = p0[288], u11 = p0[324];
                    unsigned bh0 = __byte_perm(u00, u01, 0x5410);
                    unsigned bl0 = __byte_perm(u00, u01, 0x7632);
                    unsigned bh1 = __byte_perm(u10, u11, 0x5410);
                    unsigned bl1 = __byte_perm(u10, u11, 0x7632);
                    mma16816(acc[0][nt], AH0.x, AH0.y, AH0.z, AH0.w, bh0, bh1);
                    mma16816(acc[1][nt], AH1.x, AH1.y, AH1.z, AH1.w, bh0, bh1);
                    mma16816(acc[0][nt], AH0.x, AH0.y, AH0.z, AH0.w, bl0, bl1);
                    mma16816(acc[1][nt], AH1.x, AH1.y, AH1.z, AH1.w, bl0, bl1);
                    mma16816(acc[0][nt], AL0.x, AL0.y, AL0.z, AL0.w, bh0, bh1);
                    mma16816(acc[1][nt], AL1.x, AL1.y, AL1.z, AL1.w, bh0, bh1);
                }
                if (c < 7) {
                    uint4* d = (uint4*)(hst + ((c + 1) & 1) * 4608 +
                                        krow * 36 + half * 16);
                    d[0] = pv0; d[1] = pv1; d[2] = pv2; d[3] = pv3;
                }
                NB_REC();
            }

            // ---- 2-round partial reduction in smem ----
            if (w >= 4) {
                float* buf = hp + (w - 4) * 1088;
#pragma unroll
                for (int mt = 0; mt < 2; mt++)
#pragma unroll
                    for (int nt = 0; nt < 4; nt++) {
                        int r0 = mt * 16 + g, col = nt * 8 + 2 * tg;
                        *(float2*)&buf[r0 * 34 + col] =
                            make_float2(acc[mt][nt][0], acc[mt][nt][1]);
                        *(float2*)&buf[(r0 + 8) * 34 + col] =
                            make_float2(acc[mt][nt][2], acc[mt][nt][3]);
                    }
            }
            NB_REC();
            if (w < 4) {
                float* buf = hp + w * 1088;
#pragma unroll
                for (int mt = 0; mt < 2; mt++)
#pragma unroll
                    for (int nt = 0; nt < 4; nt++) {
                        int r0 = mt * 16 + g, col = nt * 8 + 2 * tg;
                        float2 p0 = *(float2*)&buf[r0 * 34 + col];
                        float2 p1 = *(float2*)&buf[(r0 + 8) * 34 + col];
                        p0.x += acc[mt][nt][0]; p0.y += acc[mt][nt][1];
                        p1.x += acc[mt][nt][2]; p1.y += acc[mt][nt][3];
                        *(float2*)&buf[r0 * 34 + col] = p0;
                        *(float2*)&buf[(r0 + 8) * 34 + col] = p1;
                    }
            }
            NB_REC();

            // ---- fused gate epilogue: thread = (cl=w, b=eb) ----
            float gv[4];
#pragma unroll
            for (int gate = 0; gate < 4; gate++) {
                int ro = (gate * 8 + w) * 34 + eb;
                gv[gate] = hp[ro] + hp[1088 + ro] + hp[2176 + ro] + hp[3264 + ro];
            }
            float gi = x_i + gv[0], gf = x_f + gv[1];
            float gg = x_g + gv[2], go = x_o + gv[3];
            float ig = 1.f / (1.f + __expf(-gi));
            float fg = 1.f / (1.f + __expf(-gf));
            float gt = tanhf(gg);
            float og = 1.f / (1.f + __expf(-go));
            c_state  = fg * c_state + ig * gt;
            float hn = og * tanhf(c_state);

            out[((size_t)t * BB + eb) * KD + ec] = hn;
            // packed coalesced h store: [k][b]
            {
                __nv_bfloat16 hb = __float2bfloat16_rn(hn);
                __nv_bfloat16 lb = __float2bfloat16_rn(hn - __bfloat162float(hb));
                unsigned up = (unsigned)*(unsigned short*)&hb |
                              ((unsigned)*(unsigned short*)&lb << 16);
                asm volatile("st.global.cg.u32 [%0], %1;"
                             :: "l"(&hout[ec * 32 + eb]), "r"(up) : "memory");
            }

            // ---- release: group counter (CG grid-sync pattern) ----
            if (t != TT - 1) {
                NB_REC();
                if (tid == 0) red_rel(&g_ckcnt[mygrp], 1u);
            }
        }
    } else {
        // ============ XPROJ PRODUCER (warps 8-15): bf16-split HMMA ==========
        const int tid2 = tid - 256;
        const int x_b  = blk & 31;
        const int y_b  = blk >> 5;
        const int bn   = x_b * 128;

        const int wid2 = tid2 >> 5;
        const int lane = tid2 & 31;
        const int wm   = wid2 >> 2;
        const int wn   = wid2 & 3;
        const int g    = lane >> 2;
        const int tg   = lane & 3;

        const int srow = tid2 >> 2;
        const int seg  = tid2 & 3;

        float bias0[4], bias1[4];
#pragma unroll
        for (int nf = 0; nf < 4; nf++) {
            int cc = bn + wn * 32 + nf * 8 + 2 * tg;
            bias0[nf] = __ldg(&b_ih[cc])     + __ldg(&b_hh[cc]);
            bias1[nf] = __ldg(&b_ih[cc + 1]) + __ldg(&b_hh[cc + 1]);
        }

        __nv_bfloat16* stg[2] = { gx, gx + 10240 };

        const float4* Wg0 = (const float4*)(w_ih + (size_t)(bn + srow) * KD + seg * 4);
        const float4* Wg1 = (const float4*)(w_ih + (size_t)(bn + srow + 64) * KD + seg * 4);

        for (int it = 0; it < 32; it++) {
            const int y  = y_b + 4 * it;
            const int bm = y * 128;
            const float4* Ag0 = (const float4*)(embs + (size_t)(bm + srow) * KD + seg * 4);
            const float4* Ag1 = (const float4*)(embs + (size_t)(bm + srow + 64) * KD + seg * 4);

            float acc[4][4][4];
#pragma unroll
            for (int i = 0; i < 4; i++)
#pragma unroll
                for (int j = 0; j < 4; j++)
#pragma unroll
                    for (int q = 0; q < 4; q++) acc[i][j][q] = 0.f;

            {
                float4 a0 = __ldg(Ag0), a1 = __ldg(Ag1);
                float4 w0 = __ldg(Wg0), w1 = __ldg(Wg1);
                __nv_bfloat16* Ahi = stg[0];
                __nv_bfloat16* Alo = stg[0] + 2560;
                __nv_bfloat16* Whi = stg[0] + 5120;
                __nv_bfloat16* Wlo = stg[0] + 7680;
                cvt_store_slab(Ahi, Alo, srow,      seg, a0);
                cvt_store_slab(Ahi, Alo, srow + 64, seg, a1);
                cvt_store_slab(Whi, Wlo, srow,      seg, w0);
                cvt_store_slab(Whi, Wlo, srow + 64, seg, w1);
            }
            NB_GEM();

            for (int s = 0; s < 64; s++) {
                float4 a0, a1, w0, w1;
                if (s < 63) {
                    a0 = __ldg(Ag0 + (s + 1) * 4);
                    a1 = __ldg(Ag1 + (s + 1) * 4);
                    w0 = __ldg(Wg0 + (s + 1) * 4);
                    w1 = __ldg(Wg1 + (s + 1) * 4);
                }

                const __nv_bfloat16* base = stg[s & 1];
                const unsigned* Ahi = (const unsigned*)(base);
                const unsigned* Alo = (const unsigned*)(base + 2560);
                const unsigned* Whi = (const unsigned*)(base + 5120);
                const unsigned* Wlo = (const unsigned*)(base + 7680);

                unsigned bh[4][2], bl[4][2];
#pragma unroll
                for (int nf = 0; nf < 4; nf++) {
                    int nrow = wn * 32 + nf * 8 + g;
                    bh[nf][0] = Whi[nrow * 10 + tg];
                    bh[nf][1] = Whi[nrow * 10 + tg + 4];
                    bl[nf][0] = Wlo[nrow * 10 + tg];
                    bl[nf][1] = Wlo[nrow * 10 + tg + 4];
                }
#pragma unroll
                for (int mf = 0; mf < 4; mf++) {
                    int ar = (wm * 64 + mf * 16 + g) * 10;
                    unsigned a0f = Ahi[ar + tg];
                    unsigned a1f = Ahi[ar + 80 + tg];
                    unsigned a2f = Ahi[ar + tg + 4];
                    unsigned a3f = Ahi[ar + 80 + tg + 4];
#pragma unroll
                    for (int nf = 0; nf < 4; nf++) {
                        mma16816(acc[mf][nf], a0f, a1f, a2f, a3f, bh[nf][0], bh[nf][1]);
                        mma16816(acc[mf][nf], a0f, a1f, a2f, a3f, bl[nf][0], bl[nf][1]);
                    }
                }
#pragma unroll
                for (int mf = 0; mf < 4; mf++) {
                    int ar = (wm * 64 + mf * 16 + g) * 10;
                    unsigned a0f = Alo[ar + tg];
                    unsigned a1f = Alo[ar + 80 + tg];
                    unsigned a2f = Alo[ar + tg + 4];
                    unsigned a3f = Alo[ar + 80 + tg + 4];
#pragma unroll
                    for (int nf = 0; nf < 4; nf++) {
                        mma16816(acc[mf][nf], a0f, a1f, a2f, a3f, bh[nf][0], bh[nf][1]);
                    }
                }

                if (s < 63) {
                    __nv_bfloat16* nb = stg[(s + 1) & 1];
                    cvt_store_slab(nb,        nb + 2560, srow,      seg, a0);
                    cvt_store_slab(nb,        nb + 2560, srow + 64, seg, a1);
                    cvt_store_slab(nb + 5120, nb + 7680, srow,      seg, w0);
                    cvt_store_slab(nb + 5120, nb + 7680, srow + 64, seg, w1);
                }
                NB_GEM();
            }

#pragma unroll
            for (int mf = 0; mf < 4; mf++) {
                int r0 = bm + wm * 64 + mf * 16 + g;
#pragma unroll
                for (int nf = 0; nf < 4; nf++) {
                    int cc = bn + wn * 32 + nf * 8 + 2 * tg;
                    float2 v0, v1;
                    v0.x = acc[mf][nf][0] + bias0[nf];
                    v0.y = acc[mf][nf][1] + bias1[nf];
                    v1.x = acc[mf][nf][2] + bias0[nf];
                    v1.y = acc[mf][nf][3] + bias1[nf];
                    __stcg((float2*)&g_xproj[(size_t)r0 * GD + cc], v0);
                    __stcg((float2*)&g_xproj[(size_t)(r0 + 8) * GD + cc], v1);
                }
            }

            __threadfence();
            NB_GEM();
            if (tid2 == 0) red_rel(&g_xflag[y], 1u);
        }
    }
}

// ---------------------------------------------------------------------------
extern "C" void kernel_launch(void* const* d_in, const int* in_sizes, int n_in,
                              void* d_out, int out_size) {
    const float* embs = (const float*)d_in[0];
    const float* w_ih = (const float*)d_in[1];
    const float* w_hh = (const float*)d_in[2];
    const float* b_ih = (const float*)d_in[3];
    const float* b_hh = (const float*)d_in[4];
    const float* h0   = (const float*)d_in[5];
    const float* c0   = (const float*)d_in[6];
    float* out = (float*)d_out;

    init_state_kernel<<<128, 256>>>(h0);

    static int smem_set = 0;
    const int smem_bytes = SMEM_WORDS * (int)sizeof(float);  // 226304 B
    if (!smem_set) {
        cudaFuncSetAttribute(lstm_fused_kernel,
                             cudaFuncAttributeMaxDynamicSharedMemorySize,
                             smem_bytes);
        smem_set = 1;
    }
    lstm_fused_kernel<<<NBLK, NTHR, smem_bytes>>>(embs, w_ih, w_hh, b_ih, b_hh,
                                                  c0, out);
}